// round 5
// baseline (speedup 1.0000x reference)
#include <cuda_runtime.h>
#include <cuda_bf16.h>

// Problem constants (fixed by the reference)
#define BB  4
#define LL  512
#define HH  768
#define SS  100
#define RR  100
#define EE  25
#define NEC 10              // entity classes
#define NRC 6               // relation classes
#define NEGV (-1e20f)

#define H4       (HH/4)     // 192 float4 lanes per hidden row
#define SPAN_DIM (HH + EE)  // 793
#define NENT     (BB*SS)    // 400 entity blocks
#define NREL     (BB*RR)    // 400 relation-context blocks
#define GRID     (NENT + NREL)

// w_rel row layout: [ctx 0..768 | ent_hi 768..1536 | ent_ti 1536..2304 | sz_hi 2304..2329 | sz_ti 2329..2354]
#define WR_HEAD_OFF  (768*NRC)    // 4608 floats
#define WR_TAIL_OFF  (1536*NRC)   // 9216
#define WR_SZH_OFF   (2304*NRC)   // 13824
#define WR_SZT_OFF   (2329*NRC)   // 13974
#define P_SLICE_FL   (SPAN_DIM*NRC)   // 4758 floats per projection slice (793*6)

// Scratch: per-entity head/tail projections (no runtime allocation)
__device__ float g_p1[NENT*NRC];
__device__ float g_p2[NENT*NRC];
__device__ int   g_count = 0;

__global__ void __launch_bounds__(256)
spert_fused_kernel(const float* __restrict__ hid,
                   const int*   __restrict__ emask,
                   const int*   __restrict__ rel,
                   const int*   __restrict__ cmask,
                   const float* __restrict__ size_emb,
                   const float* __restrict__ w_span,
                   const float* __restrict__ b_span,
                   const float* __restrict__ w_rel,
                   const float* __restrict__ b_rel,
                   float*       __restrict__ out)
{
    __shared__ __align__(16) float sw[2*P_SLICE_FL];   // 9516 floats (38 KB) staged weights
    __shared__ __align__(16) float repr[SPAN_DIM];
    __shared__ float sred[8][12];
    __shared__ int s_start, s_len, s_last;

    const int bid    = blockIdx.x;
    const bool is_ent = (bid < NENT);
    const int idx    = is_ent ? bid : bid - NENT;    // b*N + n
    const int b      = idx / SS;
    const int t      = threadIdx.x;
    const int warp   = t >> 5, lane = t & 31;

    // ---- recover contiguous span (start, len) from the 0/1 mask row ----
    const int* mrow = (is_ent ? emask : cmask) + (size_t)idx * LL;
    if (t == 0) { s_start = LL; s_len = 0; }
    __syncthreads();
    for (int l = t; l < LL; l += 256)
        if (mrow[l]) { atomicAdd(&s_len, 1); atomicMin(&s_start, l); }
    __syncthreads();
    const int start = s_start;
    const int len   = s_len;

    // ---- masked max pool over the span (float4, 192 lanes) ----
    if (t < H4) {
        float4 mx = make_float4(NEGV, NEGV, NEGV, NEGV);
        const float4* hbase = reinterpret_cast<const float4*>(hid + (size_t)b * LL * HH) + t;
        for (int l = start; l < start + len; ++l) {
            float4 v = hbase[(size_t)l * H4];
            mx.x = fmaxf(mx.x, v.x); mx.y = fmaxf(mx.y, v.y);
            mx.z = fmaxf(mx.z, v.z); mx.w = fmaxf(mx.w, v.w);
        }
        reinterpret_cast<float4*>(repr)[t] = mx;
    }

    if (is_ent) {
        if (t < EE) repr[HH + t] = size_emb[len * EE + t];

        // ===== phase A: entity logits  (repr(793) @ w_span(793x10)) =====
        {   // stage w_span into shared, coalesced float2
            const float2* src = reinterpret_cast<const float2*>(w_span);
            for (int i = t; i < SPAN_DIM*NEC/2; i += 256)   // 3965 float2
                reinterpret_cast<float2*>(sw)[i] = src[i];
        }
        __syncthreads();

        float acc[NEC];
        #pragma unroll
        for (int j = 0; j < NEC; ++j) acc[j] = 0.f;
        for (int k = t; k < SPAN_DIM; k += 256) {
            float rv = repr[k];
            #pragma unroll
            for (int j = 0; j < NEC; ++j) acc[j] += rv * sw[k*NEC + j];
        }
        #pragma unroll
        for (int j = 0; j < NEC; ++j) {
            float v = acc[j];
            #pragma unroll
            for (int o = 16; o; o >>= 1) v += __shfl_down_sync(0xffffffffu, v, o);
            if (lane == 0) sred[warp][j] = v;
        }
        __syncthreads();
        if (t < NEC) {
            float s = 0.f;
            #pragma unroll
            for (int w = 0; w < 8; ++w) s += sred[w][t];
            out[idx*NEC + t] = s + b_span[t];
        }
        __syncthreads();   // sw/sred reuse barrier

        // ===== phase B: head/tail projections  (repr @ W_head, repr @ W_tail) =====
        {   // p1 slice: rows [768,1536) ++ rows [2304,2329)  -> sw[0 .. 4758)
            for (int i = t; i < P_SLICE_FL/2; i += 256) {   // 2379 float2
                float2 v = (i < 2304)
                    ? reinterpret_cast<const float2*>(w_rel + WR_HEAD_OFF)[i]
                    : reinterpret_cast<const float2*>(w_rel + WR_SZH_OFF)[i - 2304];
                reinterpret_cast<float2*>(sw)[i] = v;
            }
            // p2 slice: rows [1536,2304) ++ rows [2329,2354) -> sw[4758 .. 9516)
            for (int i = t; i < P_SLICE_FL/2; i += 256) {
                float2 v = (i < 2304)
                    ? reinterpret_cast<const float2*>(w_rel + WR_TAIL_OFF)[i]
                    : reinterpret_cast<const float2*>(w_rel + WR_SZT_OFF)[i - 2304];
                reinterpret_cast<float2*>(sw)[P_SLICE_FL/2 + i] = v;
            }
        }
        __syncthreads();

        float a1[NRC], a2[NRC];
        #pragma unroll
        for (int j = 0; j < NRC; ++j) { a1[j] = 0.f; a2[j] = 0.f; }
        for (int k = t; k < SPAN_DIM; k += 256) {
            float rv = repr[k];
            #pragma unroll
            for (int j = 0; j < NRC; ++j) {
                a1[j] += rv * sw[k*NRC + j];
                a2[j] += rv * sw[P_SLICE_FL + k*NRC + j];
            }
        }
        #pragma unroll
        for (int j = 0; j < NRC; ++j) {
            float v1 = a1[j], v2 = a2[j];
            #pragma unroll
            for (int o = 16; o; o >>= 1) {
                v1 += __shfl_down_sync(0xffffffffu, v1, o);
                v2 += __shfl_down_sync(0xffffffffu, v2, o);
            }
            if (lane == 0) { sred[warp][j] = v1; sred[warp][6 + j] = v2; }
        }
        __syncthreads();
        if (t < 2*NRC) {
            float s = 0.f;
            #pragma unroll
            for (int w = 0; w < 8; ++w) s += sred[w][t];
            if (t < NRC) g_p1[idx*NRC + t]         = s;
            else         g_p2[idx*NRC + (t - NRC)] = s;
        }
    } else {
        // ===== relation-context block: ctx(768) @ W_ctx(768x6) + bias =====
        {   // stage w_rel rows [0,768) -> 4608 floats
            const float2* src = reinterpret_cast<const float2*>(w_rel);
            for (int i = t; i < WR_HEAD_OFF/2; i += 256)    // 2304 float2
                reinterpret_cast<float2*>(sw)[i] = src[i];
        }
        __syncthreads();

        float acc[NRC];
        #pragma unroll
        for (int j = 0; j < NRC; ++j) acc[j] = 0.f;
        for (int k = t; k < HH; k += 256) {
            float rv = repr[k];
            #pragma unroll
            for (int j = 0; j < NRC; ++j) acc[j] += rv * sw[k*NRC + j];
        }
        #pragma unroll
        for (int j = 0; j < NRC; ++j) {
            float v = acc[j];
            #pragma unroll
            for (int o = 16; o; o >>= 1) v += __shfl_down_sync(0xffffffffu, v, o);
            if (lane == 0) sred[warp][j] = v;
        }
        __syncthreads();
        if (t < NRC) {
            float s = 0.f;
            #pragma unroll
            for (int w = 0; w < 8; ++w) s += sred[w][t];
            out[NENT*NEC + idx*NRC + t] = s + b_rel[t];
        }
    }

    // ===== last-block-done combine: rel_logits += p1[hi] + p2[ti] =====
    __threadfence();
    __syncthreads();
    if (t == 0)
        s_last = (atomicAdd(&g_count, 1) == GRID - 1) ? 1 : 0;
    __syncthreads();

    if (s_last) {
        __threadfence();
        for (int i = t; i < NREL*NRC; i += 256) {
            int rid = i / NRC, j = i - rid*NRC;
            int bb  = rid / RR;
            int hi  = rel[rid*2 + 0];
            int ti  = rel[rid*2 + 1];
            out[NENT*NEC + i] += g_p1[(bb*SS + hi)*NRC + j]
                               + g_p2[(bb*SS + ti)*NRC + j];
        }
        if (t == 0) g_count = 0;   // reset for next graph replay
    }
}

// -----------------------------------------------------------------------------
// kernel_launch: inputs per metadata order:
//   0 hidden_states (f32)  1 entity_masks (i32)  2 relations (i32)
//   3 relation_context_masks (i32)  4 size_emb (f32)
//   5 w_span (f32)  6 b_span (f32)  7 w_rel (f32)  8 b_rel (f32)
// out: 6400 f32 = entity_logits (4000) ++ relation_logits (2400)
// -----------------------------------------------------------------------------
extern "C" void kernel_launch(void* const* d_in, const int* in_sizes, int n_in,
                              void* d_out, int out_size)
{
    const float* hid      = (const float*)d_in[0];
    const int*   emask    = (const int*)  d_in[1];
    const int*   rel      = (const int*)  d_in[2];
    const int*   cmask    = (const int*)  d_in[3];
    const float* size_emb = (const float*)d_in[4];
    const float* w_span   = (const float*)d_in[5];
    const float* b_span   = (const float*)d_in[6];
    const float* w_rel    = (const float*)d_in[7];
    const float* b_rel    = (const float*)d_in[8];
    float* out = (float*)d_out;

    spert_fused_kernel<<<GRID, 256>>>(hid, emask, rel, cmask, size_emb,
                                      w_span, b_span, w_rel, b_rel, out);
}

// round 6
// speedup vs baseline: 1.2154x; 1.2154x over previous
#include <cuda_runtime.h>
#include <cuda_bf16.h>

// Problem constants (fixed by the reference)
#define BB  4
#define LL  512
#define HH  768
#define SS  100
#define RR  100
#define EE  25
#define NEC 10              // entity classes
#define NRC 6               // relation classes
#define NEGV (-1e20f)

#define H4       (HH/4)     // 192 float4 lanes per hidden row
#define SPAN_DIM (HH + EE)  // 793
#define REL_DIM  (3*HH + 2*EE)  // 2354
#define NENT     (BB*SS)    // 400
#define NREL     (BB*RR)    // 400

// Scratch (static device globals — no runtime allocation)
__device__ float g_ent[NENT*HH];            // pooled entity reprs
__device__ float g_esz[NENT*EE];            // entity size embeddings
__device__ float g_ctx[NREL*HH];            // pooled relation-context reprs
__device__ float g_wspanT[NEC*SPAN_DIM];    // w_span transposed: [j][k]
__device__ float g_wrelT [NRC*REL_DIM];     // w_rel  transposed: [j][k]

// -----------------------------------------------------------------------------
// Kernel A: pooling (blocks 0..799) + weight transpose (blocks 800..802)
// -----------------------------------------------------------------------------
__global__ void __launch_bounds__(256)
spert_pool_kernel(const float* __restrict__ hid,
                  const int*   __restrict__ emask,
                  const int*   __restrict__ cmask,
                  const float* __restrict__ size_emb,
                  const float* __restrict__ w_span,
                  const float* __restrict__ w_rel)
{
    const int bid = blockIdx.x;
    const int t   = threadIdx.x;

    // ---- weight transpose blocks ----
    if (bid >= NENT + NREL) {
        int which = bid - (NENT + NREL);
        if (which == 0) {
            // w_span (793x10) -> g_wspanT (10x793)
            for (int i = t; i < SPAN_DIM*NEC; i += 256) {
                int k = i / NEC, j = i - k*NEC;
                g_wspanT[j*SPAN_DIM + k] = w_span[i];
            }
        } else {
            // w_rel (2354x6) -> g_wrelT (6x2354), split across 2 blocks
            int half = (REL_DIM*NRC) / 2;                 // 7062
            int base = (which - 1) * half;
            for (int i = base + t; i < base + half; i += 256) {
                int k = i / NRC, j = i - k*NRC;
                g_wrelT[j*REL_DIM + k] = w_rel[i];
            }
        }
        return;
    }

    __shared__ int s_start, s_len;
    const bool is_ent = (bid < NENT);
    const int idx = is_ent ? bid : bid - NENT;      // b*N + n
    const int b   = idx / SS;

    // ---- recover contiguous span (start, len) from the 0/1 mask row ----
    const int* mrow = (is_ent ? emask : cmask) + (size_t)idx * LL;
    if (t == 0) { s_start = LL; s_len = 0; }
    __syncthreads();
    for (int l = t; l < LL; l += 256)
        if (mrow[l]) { atomicAdd(&s_len, 1); atomicMin(&s_start, l); }
    __syncthreads();
    const int start = s_start;
    const int len   = s_len;

    // ---- masked max pool over the span (float4, 192 lanes) ----
    if (t < H4) {
        float4 mx = make_float4(NEGV, NEGV, NEGV, NEGV);
        const float4* hbase = reinterpret_cast<const float4*>(hid + (size_t)b * LL * HH) + t;
        for (int l = start; l < start + len; ++l) {
            float4 v = hbase[(size_t)l * H4];
            mx.x = fmaxf(mx.x, v.x); mx.y = fmaxf(mx.y, v.y);
            mx.z = fmaxf(mx.z, v.z); mx.w = fmaxf(mx.w, v.w);
        }
        float4* dst = reinterpret_cast<float4*>((is_ent ? g_ent : g_ctx) + (size_t)idx * HH);
        dst[t] = mx;
    }
    if (is_ent && t < EE)
        g_esz[idx*EE + t] = size_emb[len*EE + t];
}

// -----------------------------------------------------------------------------
// Kernel B: logits. blocks 0..399 entity, 400..799 relation.
// Warp-per-output-column dots; weights read coalesced from transposed scratch
// (L1-resident across blocks). Entity path: no smem, no barriers.
// -----------------------------------------------------------------------------
__global__ void __launch_bounds__(256)
spert_logits_kernel(const int*   __restrict__ rel,
                    const float* __restrict__ b_span,
                    const float* __restrict__ b_rel,
                    float*       __restrict__ out)
{
    const int bid  = blockIdx.x;
    const int t    = threadIdx.x;
    const int warp = t >> 5, lane = t & 31;

    if (bid < NENT) {
        // ===== entity logits: repr(793) @ w_span -> out[bid][0..10) =====
        const int idx = bid;
        const float* ent = g_ent + (size_t)idx * HH;
        const float* esz = g_esz + (size_t)idx * EE;

        for (int j = warp; j < NEC; j += 8) {
            const float* wj = g_wspanT + (size_t)j * SPAN_DIM;
            float acc = 0.f;
            #pragma unroll 5
            for (int k = lane; k < SPAN_DIM; k += 32) {
                float rv = (k < HH) ? ent[k] : esz[k - HH];
                acc += rv * wj[k];
            }
            #pragma unroll
            for (int o = 16; o; o >>= 1)
                acc += __shfl_down_sync(0xffffffffu, acc, o);
            if (lane == 0)
                out[idx*NEC + j] = acc + b_span[j];
        }
        return;
    }

    // ===== relation logits: [ctx|ent_h|ent_t|sz_h|sz_t](2354) @ w_rel =====
    __shared__ __align__(16) float repr[REL_DIM];

    const int idx = bid - NENT;          // b*R + r
    const int b   = idx / RR;
    const int hi  = rel[idx*2 + 0];
    const int ti  = rel[idx*2 + 1];

    const float4* ctx = reinterpret_cast<const float4*>(g_ctx + (size_t)idx * HH);
    const float4* eh  = reinterpret_cast<const float4*>(g_ent + (size_t)(b*SS + hi) * HH);
    const float4* et  = reinterpret_cast<const float4*>(g_ent + (size_t)(b*SS + ti) * HH);

    if (t < H4) {
        reinterpret_cast<float4*>(repr)[t]          = ctx[t];
        reinterpret_cast<float4*>(repr)[H4 + t]     = eh[t];
        reinterpret_cast<float4*>(repr)[2*H4 + t]   = et[t];
    }
    if (t < EE) {
        repr[3*HH + t]      = g_esz[(b*SS + hi)*EE + t];
        repr[3*HH + EE + t] = g_esz[(b*SS + ti)*EE + t];
    }
    __syncthreads();

    for (int j = warp; j < NRC; j += 8) {
        const float* wj = g_wrelT + (size_t)j * REL_DIM;
        float acc = 0.f;
        #pragma unroll 8
        for (int k = lane; k < REL_DIM; k += 32)
            acc += repr[k] * wj[k];
        #pragma unroll
        for (int o = 16; o; o >>= 1)
            acc += __shfl_down_sync(0xffffffffu, acc, o);
        if (lane == 0)
            out[NENT*NEC + idx*NRC + j] = acc + b_rel[j];
    }
}

// -----------------------------------------------------------------------------
// kernel_launch: inputs per metadata order:
//   0 hidden_states (f32)  1 entity_masks (i32)  2 relations (i32)
//   3 relation_context_masks (i32)  4 size_emb (f32)
//   5 w_span (f32)  6 b_span (f32)  7 w_rel (f32)  8 b_rel (f32)
// out: 6400 f32 = entity_logits (4000) ++ relation_logits (2400)
// -----------------------------------------------------------------------------
extern "C" void kernel_launch(void* const* d_in, const int* in_sizes, int n_in,
                              void* d_out, int out_size)
{
    const float* hid      = (const float*)d_in[0];
    const int*   emask    = (const int*)  d_in[1];
    const int*   rel      = (const int*)  d_in[2];
    const int*   cmask    = (const int*)  d_in[3];
    const float* size_emb = (const float*)d_in[4];
    const float* w_span   = (const float*)d_in[5];
    const float* b_span   = (const float*)d_in[6];
    const float* w_rel    = (const float*)d_in[7];
    const float* b_rel    = (const float*)d_in[8];
    float* out = (float*)d_out;

    spert_pool_kernel<<<NENT + NREL + 3, 256>>>(hid, emask, cmask, size_emb,
                                                w_span, w_rel);
    spert_logits_kernel<<<NENT + NREL, 256>>>(rel, b_span, b_rel, out);
}

// round 7
// speedup vs baseline: 1.5456x; 1.2718x over previous
#include <cuda_runtime.h>
#include <cuda_bf16.h>

// Problem constants (fixed by the reference)
#define BB  4
#define LL  512
#define HH  768
#define SS  100
#define RR  100
#define EE  25
#define NEC 10              // entity classes
#define NRC 6               // relation classes
#define NEGV (-1e20f)

#define H4       (HH/4)         // 192 float4 lanes per hidden row
#define SPAN_DIM (HH + EE)      // 793
#define REL_DIM  (3*HH + 2*EE)  // 2354
#define SPAN_PAD 800            // padded (mult of 4), zero tail
#define REL_PAD  2368           // padded (mult of 4), zero tail
#define NENT     (BB*SS)        // 400
#define NREL     (BB*RR)        // 400

// Scratch (static device globals — no runtime allocation)
__device__ float g_ent[NENT*HH];              // pooled entity reprs
__device__ float g_esz[NENT*EE];              // entity size embeddings
__device__ float g_ctx[NREL*HH];              // pooled relation-context reprs
__device__ float g_wspanT[NEC*SPAN_PAD];      // w_span^T, rows padded+zeroed
__device__ float g_wrelT [NRC*REL_PAD];       // w_rel^T,  rows padded+zeroed

// -----------------------------------------------------------------------------
// Kernel A: pooling (blocks 0..799) + padded weight transpose (blocks 800..802)
// -----------------------------------------------------------------------------
__global__ void __launch_bounds__(256)
spert_pool_kernel(const float* __restrict__ hid,
                  const int*   __restrict__ emask,
                  const int*   __restrict__ cmask,
                  const float* __restrict__ size_emb,
                  const float* __restrict__ w_span,
                  const float* __restrict__ w_rel)
{
    const int bid = blockIdx.x;
    const int t   = threadIdx.x;

    // ---- weight transpose blocks (zero-padded rows) ----
    if (bid >= NENT + NREL) {
        int which = bid - (NENT + NREL);
        if (which == 0) {
            for (int i = t; i < NEC*SPAN_PAD; i += 256) {
                int j = i / SPAN_PAD, k = i - j*SPAN_PAD;
                g_wspanT[i] = (k < SPAN_DIM) ? w_span[k*NEC + j] : 0.f;
            }
        } else {
            int half = (NRC*REL_PAD) / 2;        // 7104
            int base = (which - 1) * half;
            for (int i = base + t; i < base + half; i += 256) {
                int j = i / REL_PAD, k = i - j*REL_PAD;
                g_wrelT[i] = (k < REL_DIM) ? w_rel[k*NRC + j] : 0.f;
            }
        }
        return;
    }

    __shared__ int s_start;
    const bool is_ent = (bid < NENT);
    const int idx  = is_ent ? bid : bid - NENT;   // b*N + n
    const int b    = idx / SS;
    const int lane = t & 31, warp = t >> 5;

    // ---- recover contiguous span (start, len): ballot min + syncthreads_count ----
    const int* mrow = (is_ent ? emask : cmask) + (size_t)idx * LL;
    const int m0 = mrow[t];
    const int m1 = mrow[t + 256];
    if (t == 0) s_start = LL;
    __syncthreads();
    unsigned bal0 = __ballot_sync(0xffffffffu, m0 != 0);
    unsigned bal1 = __ballot_sync(0xffffffffu, m1 != 0);
    if (lane == 0) {
        if (bal0) atomicMin(&s_start, (warp << 5) + __ffs(bal0) - 1);
        if (bal1) atomicMin(&s_start, 256 + (warp << 5) + __ffs(bal1) - 1);
    }
    const int len = __syncthreads_count(m0 != 0) + __syncthreads_count(m1 != 0);
    const int start = s_start;   // visible: barrier above orders the atomics

    // ---- masked max pool over span (float4, unroll 4 for MLP) ----
    if (t < H4) {
        float4 mx = make_float4(NEGV, NEGV, NEGV, NEGV);
        const float4* hb = reinterpret_cast<const float4*>(hid + (size_t)b * LL * HH) + t;
        int l = start, e = start + len;
        for (; l + 4 <= e; l += 4) {
            float4 v0 = hb[(size_t)(l+0) * H4];
            float4 v1 = hb[(size_t)(l+1) * H4];
            float4 v2 = hb[(size_t)(l+2) * H4];
            float4 v3 = hb[(size_t)(l+3) * H4];
            mx.x = fmaxf(fmaxf(mx.x, v0.x), fmaxf(v1.x, fmaxf(v2.x, v3.x)));
            mx.y = fmaxf(fmaxf(mx.y, v0.y), fmaxf(v1.y, fmaxf(v2.y, v3.y)));
            mx.z = fmaxf(fmaxf(mx.z, v0.z), fmaxf(v1.z, fmaxf(v2.z, v3.z)));
            mx.w = fmaxf(fmaxf(mx.w, v0.w), fmaxf(v1.w, fmaxf(v2.w, v3.w)));
        }
        for (; l < e; ++l) {
            float4 v = hb[(size_t)l * H4];
            mx.x = fmaxf(mx.x, v.x); mx.y = fmaxf(mx.y, v.y);
            mx.z = fmaxf(mx.z, v.z); mx.w = fmaxf(mx.w, v.w);
        }
        float4* dst = reinterpret_cast<float4*>((is_ent ? g_ent : g_ctx) + (size_t)idx * HH);
        dst[t] = mx;
    }
    if (is_ent && t < EE)
        g_esz[idx*EE + t] = size_emb[len*EE + t];
}

// -----------------------------------------------------------------------------
// Kernel B: logits. All-256-thread float4 strided dots, barrier-free mainloop,
// perfectly coalesced LDG.128 from padded transposed weights (L1-resident).
// -----------------------------------------------------------------------------
__global__ void __launch_bounds__(256)
spert_logits_kernel(const int*   __restrict__ rel,
                    const float* __restrict__ b_span,
                    const float* __restrict__ b_rel,
                    float*       __restrict__ out)
{
    __shared__ float sred[8][NEC];
    const int bid  = blockIdx.x;
    const int t    = threadIdx.x;
    const int warp = t >> 5, lane = t & 31;

    if (bid < NENT) {
        // ===== entity logits: repr(793) @ w_span -> out[bid][0..10) =====
        const int idx = bid;
        const float4* ent4 = reinterpret_cast<const float4*>(g_ent + (size_t)idx * HH);
        const float*  esz  = g_esz + (size_t)idx * EE;

        float acc[NEC];
        #pragma unroll
        for (int j = 0; j < NEC; ++j) acc[j] = 0.f;

        for (int k4 = t; k4 < SPAN_PAD/4; k4 += 256) {   // 200 chunks
            const int k = k4 << 2;
            float4 rv;
            if (k < HH) {
                rv = ent4[k4];
            } else {                                      // k in [768, 800)
                rv.x = (k+0 < SPAN_DIM) ? esz[k+0-HH] : 0.f;
                rv.y = (k+1 < SPAN_DIM) ? esz[k+1-HH] : 0.f;
                rv.z = (k+2 < SPAN_DIM) ? esz[k+2-HH] : 0.f;
                rv.w = (k+3 < SPAN_DIM) ? esz[k+3-HH] : 0.f;
            }
            #pragma unroll
            for (int j = 0; j < NEC; ++j) {
                float4 w = *reinterpret_cast<const float4*>(g_wspanT + j*SPAN_PAD + k);
                acc[j] += rv.x*w.x + rv.y*w.y + rv.z*w.z + rv.w*w.w;
            }
        }
        #pragma unroll
        for (int j = 0; j < NEC; ++j) {
            float v = acc[j];
            #pragma unroll
            for (int o = 16; o; o >>= 1) v += __shfl_down_sync(0xffffffffu, v, o);
            if (lane == 0) sred[warp][j] = v;
        }
        __syncthreads();
        if (t < NEC) {
            float s = 0.f;
            #pragma unroll
            for (int w = 0; w < 8; ++w) s += sred[w][t];
            out[idx*NEC + t] = s + b_span[t];
        }
        return;
    }

    // ===== relation logits: [ctx|ent_h|ent_t|sz_h|sz_t](2354) @ w_rel =====
    const int idx = bid - NENT;          // b*R + r
    const int b   = idx / RR;
    const int hi  = rel[idx*2 + 0];
    const int ti  = rel[idx*2 + 1];

    const float4* ctx4 = reinterpret_cast<const float4*>(g_ctx + (size_t)idx * HH);
    const float4* eh4  = reinterpret_cast<const float4*>(g_ent + (size_t)(b*SS + hi) * HH);
    const float4* et4  = reinterpret_cast<const float4*>(g_ent + (size_t)(b*SS + ti) * HH);
    const float*  szh  = g_esz + (size_t)(b*SS + hi) * EE;
    const float*  szt  = g_esz + (size_t)(b*SS + ti) * EE;

    float acc[NRC];
    #pragma unroll
    for (int j = 0; j < NRC; ++j) acc[j] = 0.f;

    for (int k4 = t; k4 < REL_PAD/4; k4 += 256) {        // 592 chunks
        const int k = k4 << 2;
        float4 rv;
        if (k < HH)            rv = ctx4[k4];
        else if (k < 2*HH)     rv = eh4[k4 - H4];
        else if (k < 3*HH)     rv = et4[k4 - 2*H4];
        else {                                            // k in [2304, 2368)
            float c[4];
            #pragma unroll
            for (int i = 0; i < 4; ++i) {
                int kk = k + i;
                c[i] = (kk < 3*HH + EE) ? szh[kk - 3*HH]
                     : (kk < REL_DIM)   ? szt[kk - 3*HH - EE]
                     : 0.f;
            }
            rv = make_float4(c[0], c[1], c[2], c[3]);
        }
        #pragma unroll
        for (int j = 0; j < NRC; ++j) {
            float4 w = *reinterpret_cast<const float4*>(g_wrelT + j*REL_PAD + k);
            acc[j] += rv.x*w.x + rv.y*w.y + rv.z*w.z + rv.w*w.w;
        }
    }
    #pragma unroll
    for (int j = 0; j < NRC; ++j) {
        float v = acc[j];
        #pragma unroll
        for (int o = 16; o; o >>= 1) v += __shfl_down_sync(0xffffffffu, v, o);
        if (lane == 0) sred[warp][j] = v;
    }
    __syncthreads();
    if (t < NRC) {
        float s = 0.f;
        #pragma unroll
        for (int w = 0; w < 8; ++w) s += sred[w][t];
        out[NENT*NEC + idx*NRC + t] = s + b_rel[t];
    }
}

// -----------------------------------------------------------------------------
// kernel_launch: inputs per metadata order:
//   0 hidden_states (f32)  1 entity_masks (i32)  2 relations (i32)
//   3 relation_context_masks (i32)  4 size_emb (f32)
//   5 w_span (f32)  6 b_span (f32)  7 w_rel (f32)  8 b_rel (f32)
// out: 6400 f32 = entity_logits (4000) ++ relation_logits (2400)
// -----------------------------------------------------------------------------
extern "C" void kernel_launch(void* const* d_in, const int* in_sizes, int n_in,
                              void* d_out, int out_size)
{
    const float* hid      = (const float*)d_in[0];
    const int*   emask    = (const int*)  d_in[1];
    const int*   rel      = (const int*)  d_in[2];
    const int*   cmask    = (const int*)  d_in[3];
    const float* size_emb = (const float*)d_in[4];
    const float* w_span   = (const float*)d_in[5];
    const float* w_rel    = (const float*)d_in[7];
    const float* b_span   = (const float*)d_in[6];
    const float* b_rel    = (const float*)d_in[8];
    float* out = (float*)d_out;

    spert_pool_kernel<<<NENT + NREL + 3, 256>>>(hid, emask, cmask, size_emb,
                                                w_span, w_rel);
    spert_logits_kernel<<<NENT + NREL, 256>>>(rel, b_span, b_rel, out);
}